// round 1
// baseline (speedup 1.0000x reference)
#include <cuda_runtime.h>
#include <math.h>

// SimCLR InfoNCE + ranking metrics, fused.
//   fn = normalize(concat(feats1, feats2))          [8192, 512]
//   sim = fn @ fn^T (never materialized)
//   per row: logsumexp(sim/T, diag masked), pos = sim[i, (i+4096)%8192]/T,
//            rank = #{j != i, j != pos_idx : sim[i,j] > pos_sim}
//   outputs: (nll, acc_top1, acc_top5, acc_mean_pos) as 4 floats.

namespace {
constexpr int   N    = 8192;
constexpr int   D    = 512;
constexpr int   HALF = 4096;
constexpr float TEMP = 0.07f;
}

// Scratch (allocation-free contract: __device__ globals)
__device__ float  g_fn[N * D];            // 16 MB normalized features
__device__ float  g_pos[N];               // positive-pair cosine per row
__device__ float  g_partS[2][N];          // partial sum-of-exp per col-half
__device__ int    g_partC[2][N];          // partial rank count per col-half
__device__ double g_nll;
__device__ int    g_top1;
__device__ int    g_top5;
__device__ unsigned long long g_rank;

__global__ void k_zero() {
    g_nll = 0.0; g_top1 = 0; g_top5 = 0; g_rank = 0ull;
}

// One block per row: sumsq reduce, divide by max(norm, eps).
__global__ void k_norm(const float* __restrict__ f1, const float* __restrict__ f2) {
    const int row = blockIdx.x;
    const float* src = (row < HALF) ? (f1 + (size_t)row * D)
                                    : (f2 + (size_t)(row - HALF) * D);
    const int t = threadIdx.x;  // 128 threads, each a float4 (512 floats)
    float4 v = reinterpret_cast<const float4*>(src)[t];
    float ss = v.x * v.x + v.y * v.y + v.z * v.z + v.w * v.w;
#pragma unroll
    for (int o = 16; o; o >>= 1) ss += __shfl_xor_sync(0xffffffffu, ss, o);
    __shared__ float ws[4];
    if ((t & 31) == 0) ws[t >> 5] = ss;
    __syncthreads();
    const float tot = ws[0] + ws[1] + ws[2] + ws[3];
    const float nrm = fmaxf(sqrtf(tot), 1e-8f);
    float4 o4 = make_float4(v.x / nrm, v.y / nrm, v.z / nrm, v.w / nrm);
    reinterpret_cast<float4*>(g_fn + (size_t)row * D)[t] = o4;
}

// One warp per row: pos[i] = dot(fn[i], fn[(i+HALF) mod N])
__global__ void k_pos() {
    const int row  = blockIdx.x * 8 + (threadIdx.x >> 5);
    const int lane = threadIdx.x & 31;
    const int prow = (row + HALF) & (N - 1);
    const float4* a = reinterpret_cast<const float4*>(g_fn + (size_t)row * D);
    const float4* b = reinterpret_cast<const float4*>(g_fn + (size_t)prow * D);
    float s = 0.f;
#pragma unroll
    for (int q = 0; q < 4; q++) {
        float4 x = a[lane + q * 32];
        float4 y = b[lane + q * 32];
        s += x.x * y.x + x.y * y.y + x.z * y.z + x.w * y.w;
    }
#pragma unroll
    for (int o = 16; o; o >>= 1) s += __shfl_xor_sync(0xffffffffu, s, o);
    if (lane == 0) g_pos[row] = s;
}

// Main fused GEMM + epilogue.
// grid = (2 col-halves, 64 row-tiles), block = 256 threads.
// Block computes C tile rows [by*128, +128) x cols [bx*4096, +4096) in 32
// column tiles of 128, K-tiled by 32. 8x8 microtile per thread (16x16 grid).
// Fixed-max logsumexp: exp((sim - 1) / T), lse = log(sum) + 1/T.
__global__ void __launch_bounds__(256) k_main() {
    const int rowBase  = blockIdx.y * 128;
    const int colStart = blockIdx.x * 4096;
    __shared__ float As[32][132];  // k-major, pad 132 keeps 16B row alignment
    __shared__ float Bs[32][132];
    const int tid = threadIdx.x;
    const int tx  = tid & 15;
    const int ty  = tid >> 4;
    const float invT = 1.0f / TEMP;

    float srow[8];
    int   crow[8];
    float posv[8];
#pragma unroll
    for (int r = 0; r < 8; r++) {
        srow[r] = 0.f; crow[r] = 0;
        posv[r] = g_pos[rowBase + ty * 8 + r];
    }

    for (int ct = 0; ct < 32; ct++) {
        const int colBase = colStart + ct * 128;
        float acc[8][8];
#pragma unroll
        for (int i = 0; i < 8; i++)
#pragma unroll
            for (int j = 0; j < 8; j++) acc[i][j] = 0.f;

        for (int kt = 0; kt < 16; kt++) {
            const int kBase = kt * 32;
#pragma unroll
            for (int it = 0; it < 4; it++) {
                const int idx = it * 256 + tid;   // 0..1023
                const int r   = idx >> 3;         // 0..127
                const int kq  = idx & 7;          // 0..7 (float4 along K)
                float4 va = *reinterpret_cast<const float4*>(
                    g_fn + (size_t)(rowBase + r) * D + kBase + kq * 4);
                As[kq * 4 + 0][r] = va.x; As[kq * 4 + 1][r] = va.y;
                As[kq * 4 + 2][r] = va.z; As[kq * 4 + 3][r] = va.w;
                float4 vb = *reinterpret_cast<const float4*>(
                    g_fn + (size_t)(colBase + r) * D + kBase + kq * 4);
                Bs[kq * 4 + 0][r] = vb.x; Bs[kq * 4 + 1][r] = vb.y;
                Bs[kq * 4 + 2][r] = vb.z; Bs[kq * 4 + 3][r] = vb.w;
            }
            __syncthreads();
#pragma unroll
            for (int k = 0; k < 32; k++) {
                float a[8], b[8];
                *reinterpret_cast<float4*>(a)     = *reinterpret_cast<const float4*>(&As[k][ty * 8]);
                *reinterpret_cast<float4*>(a + 4) = *reinterpret_cast<const float4*>(&As[k][ty * 8 + 4]);
                *reinterpret_cast<float4*>(b)     = *reinterpret_cast<const float4*>(&Bs[k][tx * 8]);
                *reinterpret_cast<float4*>(b + 4) = *reinterpret_cast<const float4*>(&Bs[k][tx * 8 + 4]);
#pragma unroll
                for (int i = 0; i < 8; i++)
#pragma unroll
                    for (int j = 0; j < 8; j++)
                        acc[i][j] = fmaf(a[i], b[j], acc[i][j]);
            }
            __syncthreads();
        }

        // Fused epilogue for this 128-wide column tile
#pragma unroll
        for (int r = 0; r < 8; r++) {
            const int gi   = rowBase + ty * 8 + r;
            const int pidx = (gi + HALF) & (N - 1);
            const float pv = posv[r];
#pragma unroll
            for (int c = 0; c < 8; c++) {
                const int gj    = colBase + tx * 8 + c;
                const float sim = acc[r][c];
                const float e   = __expf((sim - 1.0f) * invT);
                if (gj != gi) {
                    srow[r] += e;
                    if (gj != pidx && sim > pv) crow[r]++;
                }
            }
        }
    }

    // Reduce the 16 threads (tx) sharing each row: contiguous half-warps.
#pragma unroll
    for (int r = 0; r < 8; r++) {
        float sv = srow[r];
        int   cv = crow[r];
#pragma unroll
        for (int o = 8; o; o >>= 1) {
            sv += __shfl_xor_sync(0xffffffffu, sv, o, 16);
            cv += __shfl_xor_sync(0xffffffffu, cv, o, 16);
        }
        if (tx == 0) {
            g_partS[blockIdx.x][rowBase + ty * 8 + r] = sv;
            g_partC[blockIdx.x][rowBase + ty * 8 + r] = cv;
        }
    }
}

// Combine the 2 column-half partials, compute per-row terms, reduce to stats.
__global__ void k_merge() {
    const int row = blockIdx.x * 256 + threadIdx.x;
    const float invT = 1.0f / TEMP;
    const float sv = g_partS[0][row] + g_partS[1][row];
    const int   cv = g_partC[0][row] + g_partC[1][row];
    const float lse  = logf(sv) + invT;            // + M0, M0 = 1/T
    const float term = lse - g_pos[row] * invT;    // -pos_logit + lse
    float wterm = term;
    int   wt1 = (cv == 0) ? 1 : 0;
    int   wt5 = (cv < 5) ? 1 : 0;
    long long wr = cv;
#pragma unroll
    for (int o = 16; o; o >>= 1) {
        wterm += __shfl_xor_sync(0xffffffffu, wterm, o);
        wt1   += __shfl_xor_sync(0xffffffffu, wt1, o);
        wt5   += __shfl_xor_sync(0xffffffffu, wt5, o);
        wr    += __shfl_xor_sync(0xffffffffu, wr, o);
    }
    __shared__ double s_term[8];
    __shared__ int    s_t1[8], s_t5[8];
    __shared__ unsigned long long s_r[8];
    const int lane = threadIdx.x & 31, w = threadIdx.x >> 5;
    if (lane == 0) {
        s_term[w] = (double)wterm; s_t1[w] = wt1; s_t5[w] = wt5;
        s_r[w] = (unsigned long long)wr;
    }
    __syncthreads();
    if (threadIdx.x == 0) {
        double a = 0.0; int b = 0, c = 0; unsigned long long d2 = 0ull;
#pragma unroll
        for (int i = 0; i < 8; i++) { a += s_term[i]; b += s_t1[i]; c += s_t5[i]; d2 += s_r[i]; }
        atomicAdd(&g_nll, a);
        atomicAdd(&g_top1, b);
        atomicAdd(&g_top5, c);
        atomicAdd(&g_rank, d2);
    }
}

__global__ void k_final(float* __restrict__ out) {
    out[0] = (float)(g_nll / (double)N);
    out[1] = (float)g_top1 / (float)N;
    out[2] = (float)g_top5 / (float)N;
    out[3] = 1.0f + (float)((double)g_rank / (double)N);
}

extern "C" void kernel_launch(void* const* d_in, const int* in_sizes, int n_in,
                              void* d_out, int out_size) {
    (void)in_sizes; (void)n_in; (void)out_size;
    const float* f1 = (const float*)d_in[0];
    const float* f2 = (const float*)d_in[1];
    float* out = (float*)d_out;

    k_zero<<<1, 1>>>();
    k_norm<<<N, 128>>>(f1, f2);
    k_pos<<<N / 8, 256>>>();
    k_main<<<dim3(2, 64), 256>>>();
    k_merge<<<N / 256, 256>>>();
    k_final<<<1, 1>>>(out);
}

// round 4
// speedup vs baseline: 5.4666x; 5.4666x over previous
#include <cuda_runtime.h>
#include <cuda_bf16.h>
#include <cstdint>
#include <math.h>

// SimCLR InfoNCE + ranking metrics via mma.sync bf16 split GEMM (sm_103-safe PTX).
//   fn = normalize(concat(feats1, feats2))  [8192, 512] fp32
//   fn = hi + lo (bf16);  sim = hi*hi^T + hi*lo^T + lo*hi^T  (fp32 accum)
//   symmetric: only lower-triangle 128x128 tiles computed; off-diag tiles
//   contribute both row-view and col-view epilogue partials.

namespace {
constexpr int   N      = 8192;
constexpr int   D      = 512;
constexpr int   HALF   = 4096;
constexpr float TEMP   = 0.07f;
constexpr int   BM     = 128;
constexpr int   BK     = 32;
constexpr int   KSTEPS = 48;         // 3 terms x 16 k-steps
constexpr int   STAGES = 4;
constexpr int   LDK    = 40;         // bf16 stride per row (80B)
constexpr int   BUFB   = BM * LDK * 2;   // 10240 B per matrix per stage
constexpr int   SMEM_DYN = STAGES * 2 * BUFB;  // 81920
constexpr int   NTILES = 64 * 65 / 2;          // 2080 lower-tri tiles
}

// ---- device scratch ----
__device__ float          g_fn[N * D];
__device__ __nv_bfloat16  g_hi[N * D];
__device__ __nv_bfloat16  g_lo[N * D];
__device__ float          g_pos[N];
__device__ float          g_rowS[N];
__device__ int            g_rowC[N];
__device__ double         g_nll;
__device__ int            g_top1;
__device__ int            g_top5;
__device__ unsigned long long g_rank;

__device__ __forceinline__ uint32_t smem_u32(const void* p) {
    uint32_t a;
    asm("{ .reg .u64 t; cvta.to.shared.u64 t, %1; cvt.u32.u64 %0, t; }" : "=r"(a) : "l"(p));
    return a;
}
#define CP16(sa, g) asm volatile("cp.async.cg.shared.global [%0], [%1], 16;" :: "r"(sa), "l"(g))
#define CP_COMMIT() asm volatile("cp.async.commit_group;")
#define CP_WAIT(n)  asm volatile("cp.async.wait_group %0;" :: "n"(n))
#define LDSM4(r0, r1, r2, r3, a)                                             \
    asm volatile("ldmatrix.sync.aligned.m8n8.x4.shared.b16 {%0,%1,%2,%3}, [%4];" \
                 : "=r"(r0), "=r"(r1), "=r"(r2), "=r"(r3) : "r"(a))
#define MMA16816(c, a, b0, b1)                                               \
    asm volatile("mma.sync.aligned.m16n8k16.row.col.f32.bf16.bf16.f32 "      \
                 "{%0,%1,%2,%3}, {%4,%5,%6,%7}, {%8,%9}, {%0,%1,%2,%3};"     \
                 : "+f"((c)[0]), "+f"((c)[1]), "+f"((c)[2]), "+f"((c)[3])    \
                 : "r"((a)[0]), "r"((a)[1]), "r"((a)[2]), "r"((a)[3]),       \
                   "r"(b0), "r"(b1))

// ---------------- small kernels ----------------
__global__ void k_zero() {
    int i = blockIdx.x * 256 + threadIdx.x;
    g_rowS[i] = 0.f; g_rowC[i] = 0;
    if (i == 0) { g_nll = 0.0; g_top1 = 0; g_top5 = 0; g_rank = 0ull; }
}

__global__ void k_norm(const float* __restrict__ f1, const float* __restrict__ f2) {
    const int row = blockIdx.x;
    const float* src = (row < HALF) ? (f1 + (size_t)row * D)
                                    : (f2 + (size_t)(row - HALF) * D);
    const int t = threadIdx.x;   // 128 threads x float4
    float4 v = reinterpret_cast<const float4*>(src)[t];
    float ss = v.x * v.x + v.y * v.y + v.z * v.z + v.w * v.w;
#pragma unroll
    for (int o = 16; o; o >>= 1) ss += __shfl_xor_sync(0xffffffffu, ss, o);
    __shared__ float ws[4];
    if ((t & 31) == 0) ws[t >> 5] = ss;
    __syncthreads();
    const float inv = 1.0f / fmaxf(sqrtf(ws[0] + ws[1] + ws[2] + ws[3]), 1e-8f);
    float x[4] = { v.x * inv, v.y * inv, v.z * inv, v.w * inv };
    reinterpret_cast<float4*>(g_fn + (size_t)row * D)[t] =
        make_float4(x[0], x[1], x[2], x[3]);
    size_t base = (size_t)row * D + t * 4;
#pragma unroll
    for (int c = 0; c < 4; c++) {
        __nv_bfloat16 h = __float2bfloat16(x[c]);
        g_hi[base + c] = h;
        g_lo[base + c] = __float2bfloat16(x[c] - __bfloat162float(h));
    }
}

__global__ void k_pos() {
    const int row  = blockIdx.x * 8 + (threadIdx.x >> 5);
    const int lane = threadIdx.x & 31;
    const int prow = (row + HALF) & (N - 1);
    const float4* a = reinterpret_cast<const float4*>(g_fn + (size_t)row * D);
    const float4* b = reinterpret_cast<const float4*>(g_fn + (size_t)prow * D);
    float s = 0.f;
#pragma unroll
    for (int q = 0; q < 4; q++) {
        float4 x = a[lane + q * 32], y = b[lane + q * 32];
        s += x.x * y.x + x.y * y.y + x.z * y.z + x.w * y.w;
    }
#pragma unroll
    for (int o = 16; o; o >>= 1) s += __shfl_xor_sync(0xffffffffu, s, o);
    if (lane == 0) g_pos[row] = s;
}

// ---------------- main: triangular-tile HMMA GEMM + fused epilogue ----------------
__global__ void __launch_bounds__(256) k_main() {
    extern __shared__ __align__(16) char dsm[];

    // decode lower-triangle tile (bi >= bj)
    const int t = blockIdx.x;
    int bi = (int)((sqrtf(8.0f * (float)t + 1.0f) - 1.0f) * 0.5f);
    while ((bi + 1) * (bi + 2) / 2 <= t) ++bi;
    while (bi * (bi + 1) / 2 > t) --bi;
    const int bj = t - bi * (bi + 1) / 2;
    const bool offd = (bi != bj);
    const int rowBase = bi * BM;
    const int colBase = bj * BM;

    const int tid  = threadIdx.x;
    const int l    = tid & 31;
    const int wid  = tid >> 5;
    const int warpM = wid & 1;    // 2 -> 64 rows
    const int warpN = wid >> 1;   // 4 -> 32 cols
    const float invT = 1.0f / TEMP;

    uint32_t aBufU[STAGES], bBufU[STAGES];
#pragma unroll
    for (int s = 0; s < STAGES; s++) {
        aBufU[s] = smem_u32(dsm + s * 2 * BUFB);
        bBufU[s] = aBufU[s] + BUFB;
    }
    // cp.async destination offsets (per thread, 2 chunks of 16B per matrix)
    uint32_t dstOff[2];
    int gRow[2], gQ[2];
#pragma unroll
    for (int i = 0; i < 2; i++) {
        int c = i * 256 + tid;
        gRow[i] = c >> 2; gQ[i] = c & 3;
        dstOff[i] = (uint32_t)(gRow[i] * (LDK * 2) + gQ[i] * 16);
    }

    // fragment smem addresses (byte offsets within a buffer)
    const uint32_t aFragOff =
        (uint32_t)(((warpM * 64 + (l & 15)) * LDK + (l >> 4) * 8) * 2);
    const uint32_t bFragOff =
        (uint32_t)(((warpN * 32 + (l & 7) + (l >> 4) * 8) * LDK + ((l >> 3) & 1) * 8) * 2);

    float acc[4][4][4];
#pragma unroll
    for (int mt = 0; mt < 4; mt++)
#pragma unroll
        for (int nt = 0; nt < 4; nt++)
#pragma unroll
            for (int r = 0; r < 4; r++) acc[mt][nt][r] = 0.f;

    // ---- pipeline ----
    auto issue = [&](int g, int b) {
        const int term = g >> 4;
        const int kb   = (g & 15) * BK;
        const __nv_bfloat16* aS = (term == 2) ? g_lo : g_hi;
        const __nv_bfloat16* bS = (term == 1) ? g_lo : g_hi;
#pragma unroll
        for (int i = 0; i < 2; i++) {
            CP16(aBufU[b] + dstOff[i],
                 aS + (size_t)(rowBase + gRow[i]) * D + kb + gQ[i] * 8);
            CP16(bBufU[b] + dstOff[i],
                 bS + (size_t)(colBase + gRow[i]) * D + kb + gQ[i] * 8);
        }
    };

#pragma unroll
    for (int g = 0; g < STAGES - 1; g++) { issue(g, g); CP_COMMIT(); }

    for (int g = 0; g < KSTEPS; ++g) {
        const int b = g & (STAGES - 1);
        CP_WAIT(STAGES - 2);
        __syncthreads();

#pragma unroll
        for (int ks = 0; ks < 2; ks++) {
            uint32_t afr[4][4];
            uint32_t bfr[2][4];
#pragma unroll
            for (int mt = 0; mt < 4; mt++)
                LDSM4(afr[mt][0], afr[mt][1], afr[mt][2], afr[mt][3],
                      aBufU[b] + aFragOff + (uint32_t)(mt * 16 * LDK * 2 + ks * 32));
#pragma unroll
            for (int np = 0; np < 2; np++)
                LDSM4(bfr[np][0], bfr[np][1], bfr[np][2], bfr[np][3],
                      bBufU[b] + bFragOff + (uint32_t)(np * 16 * LDK * 2 + ks * 32));
#pragma unroll
            for (int mt = 0; mt < 4; mt++)
#pragma unroll
                for (int nt = 0; nt < 4; nt++)
                    MMA16816(acc[mt][nt], afr[mt],
                             bfr[nt >> 1][(nt & 1) * 2], bfr[nt >> 1][(nt & 1) * 2 + 1]);
        }
        __syncthreads();
        // FIX (R3 bug): refill group g+3 belongs in buffer (g+3) mod STAGES,
        // not b+1 (which clobbered the pending next stage -> NaN).
        if (g + STAGES - 1 < KSTEPS)
            issue(g + STAGES - 1, (g + STAGES - 1) & (STAGES - 1));
        CP_COMMIT();
    }

    // ---- fused epilogue ----
    float pvR[4][2]; int piR[4][2];
    float pvC[4][2]; int piC[4][2];
    float sR[4][2], sC[4][2];
    int   cR[4][2], cC[4][2];
#pragma unroll
    for (int mt = 0; mt < 4; mt++)
#pragma unroll
        for (int h = 0; h < 2; h++) {
            int row = rowBase + warpM * 64 + mt * 16 + (l >> 2) + h * 8;
            pvR[mt][h] = g_pos[row]; piR[mt][h] = (row + HALF) & (N - 1);
            sR[mt][h] = 0.f; cR[mt][h] = 0;
        }
#pragma unroll
    for (int nt = 0; nt < 4; nt++)
#pragma unroll
        for (int e = 0; e < 2; e++) {
            int col = colBase + warpN * 32 + nt * 8 + (l & 3) * 2 + e;
            pvC[nt][e] = g_pos[col]; piC[nt][e] = (col + HALF) & (N - 1);
            sC[nt][e] = 0.f; cC[nt][e] = 0;
        }

#pragma unroll
    for (int mt = 0; mt < 4; mt++)
#pragma unroll
        for (int nt = 0; nt < 4; nt++)
#pragma unroll
            for (int r = 0; r < 4; r++) {
                const int h = r >> 1, e = r & 1;
                const int row = rowBase + warpM * 64 + mt * 16 + (l >> 2) + h * 8;
                const int col = colBase + warpN * 32 + nt * 8 + (l & 3) * 2 + e;
                const float sim = acc[mt][nt][r];
                const float ex  = __expf((sim - 1.0f) * invT);
                if (col != row) {
                    sR[mt][h] += ex;
                    if (col != piR[mt][h] && sim > pvR[mt][h]) cR[mt][h]++;
                }
                if (offd) {
                    sC[nt][e] += ex;
                    if (row != piC[nt][e] && sim > pvC[nt][e]) cC[nt][e]++;
                }
            }

    // row reductions: sum over quad lanes (xor 1,2)
#pragma unroll
    for (int mt = 0; mt < 4; mt++)
#pragma unroll
        for (int h = 0; h < 2; h++) {
            float s = sR[mt][h]; int c = cR[mt][h];
            s += __shfl_xor_sync(0xffffffffu, s, 1);
            s += __shfl_xor_sync(0xffffffffu, s, 2);
            c += __shfl_xor_sync(0xffffffffu, c, 1);
            c += __shfl_xor_sync(0xffffffffu, c, 2);
            if ((l & 3) == 0) {
                int row = rowBase + warpM * 64 + mt * 16 + (l >> 2) + h * 8;
                atomicAdd(&g_rowS[row], s);
                atomicAdd(&g_rowC[row], c);
            }
        }
    if (offd) {  // col reductions: sum over row-groups (xor 4,8,16)
#pragma unroll
        for (int nt = 0; nt < 4; nt++)
#pragma unroll
            for (int e = 0; e < 2; e++) {
                float s = sC[nt][e]; int c = cC[nt][e];
                s += __shfl_xor_sync(0xffffffffu, s, 4);
                s += __shfl_xor_sync(0xffffffffu, s, 8);
                s += __shfl_xor_sync(0xffffffffu, s, 16);
                c += __shfl_xor_sync(0xffffffffu, c, 4);
                c += __shfl_xor_sync(0xffffffffu, c, 8);
                c += __shfl_xor_sync(0xffffffffu, c, 16);
                if (l < 4) {
                    int col = colBase + warpN * 32 + nt * 8 + (l & 3) * 2 + e;
                    atomicAdd(&g_rowS[col], s);
                    atomicAdd(&g_rowC[col], c);
                }
            }
    }
}

__global__ void k_merge() {
    const int row = blockIdx.x * 256 + threadIdx.x;
    const float invT = 1.0f / TEMP;
    const float sv = g_rowS[row];
    const int   cv = g_rowC[row];
    const float term = (logf(sv) + invT) - g_pos[row] * invT;
    float wterm = term;
    int wt1 = (cv == 0) ? 1 : 0;
    int wt5 = (cv < 5) ? 1 : 0;
    long long wr = cv;
#pragma unroll
    for (int o = 16; o; o >>= 1) {
        wterm += __shfl_xor_sync(0xffffffffu, wterm, o);
        wt1   += __shfl_xor_sync(0xffffffffu, wt1, o);
        wt5   += __shfl_xor_sync(0xffffffffu, wt5, o);
        wr    += __shfl_xor_sync(0xffffffffu, wr, o);
    }
    __shared__ double s_term[8];
    __shared__ int s_t1[8], s_t5[8];
    __shared__ unsigned long long s_r[8];
    const int lane = threadIdx.x & 31, w = threadIdx.x >> 5;
    if (lane == 0) { s_term[w] = (double)wterm; s_t1[w] = wt1; s_t5[w] = wt5; s_r[w] = (unsigned long long)wr; }
    __syncthreads();
    if (threadIdx.x == 0) {
        double a = 0.0; int b = 0, c = 0; unsigned long long d2 = 0ull;
#pragma unroll
        for (int i = 0; i < 8; i++) { a += s_term[i]; b += s_t1[i]; c += s_t5[i]; d2 += s_r[i]; }
        atomicAdd(&g_nll, a);
        atomicAdd(&g_top1, b);
        atomicAdd(&g_top5, c);
        atomicAdd(&g_rank, d2);
    }
}

__global__ void k_final(float* __restrict__ out) {
    out[0] = (float)(g_nll / (double)N);
    out[1] = (float)g_top1 / (float)N;
    out[2] = (float)g_top5 / (float)N;
    out[3] = 1.0f + (float)((double)g_rank / (double)N);
}

extern "C" void kernel_launch(void* const* d_in, const int* in_sizes, int n_in,
                              void* d_out, int out_size) {
    (void)in_sizes; (void)n_in; (void)out_size;
    const float* f1 = (const float*)d_in[0];
    const float* f2 = (const float*)d_in[1];
    float* out = (float*)d_out;

    cudaFuncSetAttribute(k_main, cudaFuncAttributeMaxDynamicSharedMemorySize, SMEM_DYN);

    k_zero<<<N / 256, 256>>>();
    k_norm<<<N, 128>>>(f1, f2);
    k_pos<<<N / 8, 256>>>();
    k_main<<<NTILES, 256, SMEM_DYN>>>();
    k_merge<<<N / 256, 256>>>();
    k_final<<<1, 1>>>(out);
}